// round 8
// baseline (speedup 1.0000x reference)
#include <cuda_runtime.h>
#include <cuda_fp16.h>
#include <cstdint>

// ---------------- problem constants ----------------
#define BATCH   256
#define CIN     64
#define COUT    128
#define HX      1039
#define KNB     6
#define NSLOT   7
#define KD      448          // k extent (7 slots * 64)
#define ROWB    896          // bytes per A k-row
#define NTILE   128          // h per CTA tile
#define TPB     9            // tiles per batch: ceil(1039/128)
#define TOT2    (BATCH * TPB)     // 2304 tiles per M-half

#define A_BYTES   (64 * ROWB)     // 57344 (64 output rows resident)
#define CHUNK_B   16384           // B slot-chunk: 128 rows x 128B
#define NSTAGE    3
#define LOOKAHEAD 2
#define SMEM_TOTAL (A_BYTES + NSTAGE * CHUNK_B)   // 106496 -> 2 CTAs/SM

// ---------------- scratch ----------------
__device__ __align__(16) __half g_xTh[(size_t)BATCH * HX * CIN];  // [b][h][c], 128B rows
__device__ __align__(16) __half g_Wh[COUT * KD];                  // [o][s*64+c], 896B rows
__device__ float  g_invd[HX];

// ---------------- helpers ----------------
static __device__ __forceinline__ uint32_t s2u(const void* p) {
    uint32_t a;
    asm("{ .reg .u64 t; cvta.to.shared.u64 t, %1; cvt.u32.u64 %0, t; }" : "=r"(a) : "l"(p));
    return a;
}
static __device__ __forceinline__ void cp16cg(uint32_t dst, const void* src, uint32_t sz) {
    asm volatile("cp.async.cg.shared.global [%0], [%1], 16, %2;"
                 :: "r"(dst), "l"(src), "r"(sz) : "memory");
}
static __device__ __forceinline__ void cp16ca(uint32_t dst, const void* src) {
    asm volatile("cp.async.ca.shared.global [%0], [%1], 16;"
                 :: "r"(dst), "l"(src) : "memory");
}
static __device__ __forceinline__ void cp_commit() {
    asm volatile("cp.async.commit_group;" ::: "memory");
}
static __device__ __forceinline__ void cp_wait1() {
    asm volatile("cp.async.wait_group 1;" ::: "memory");
}
static __device__ __forceinline__ void ldsm4(uint32_t* d, uint32_t addr) {
    asm volatile("ldmatrix.sync.aligned.m8n8.x4.shared.b16 {%0,%1,%2,%3}, [%4];"
                 : "=r"(d[0]), "=r"(d[1]), "=r"(d[2]), "=r"(d[3]) : "r"(addr));
}
static __device__ __forceinline__ void mma16816(float* c, const uint32_t* a,
                                                uint32_t b0, uint32_t b1) {
    asm volatile("mma.sync.aligned.m16n8k16.row.col.f32.f16.f16.f32 "
                 "{%0,%1,%2,%3}, {%4,%5,%6,%7}, {%8,%9}, {%0,%1,%2,%3};"
                 : "+f"(c[0]), "+f"(c[1]), "+f"(c[2]), "+f"(c[3])
                 : "r"(a[0]), "r"(a[1]), "r"(a[2]), "r"(a[3]), "r"(b0), "r"(b1));
}

// ---------------- prep kernels ----------------
__global__ void prep_xTh(const float* __restrict__ x) {
    int t = blockIdx.x * blockDim.x + threadIdx.x;
    if (t >= BATCH * HX) return;
    int b = t / HX, h = t - b * HX;
    const float* src = x + (size_t)b * CIN * HX + h;
    __half2* dst = (__half2*)(g_xTh + (size_t)t * CIN);
#pragma unroll
    for (int c2 = 0; c2 < CIN / 2; c2++) {
        float v0 = src[(size_t)(2 * c2) * HX];
        float v1 = src[(size_t)(2 * c2 + 1) * HX];
        dst[c2] = __floats2half2_rn(v0, v1);
    }
}

// merged: W pack + inv counts
__global__ void prep_misc(const float* __restrict__ wc, const float* __restrict__ wn,
                          const int* __restrict__ nb) {
    int t = blockIdx.x * blockDim.x + threadIdx.x;
    if (t < COUT * KD) {
        int o = t / KD, kk = t - o * KD;
        int s = kk >> 6, cc = kk & 63;
        float v = (s == 0) ? wc[o * CIN + cc] : wn[(o * CIN + cc) * KNB + (s - 1)];
        g_Wh[t] = __float2half(v);
    }
    if (t < HX) {
        int cnt = 1;
#pragma unroll
        for (int k = 0; k < KNB; k++) cnt += (nb[t * KNB + k] >= 0) ? 1 : 0;
        g_invd[t] = 1.0f / (float)cnt;
    }
}

// ---------------- gather one 16KB B slot-chunk (4 cp16 per thread) ----------------
static __device__ __forceinline__ void gather_chunk(uint32_t buf, const int* __restrict__ nb,
                                                    int b, int hbase, int s, int tid) {
#pragma unroll
    for (int r = 0; r < 4; r++) {
        int u = tid + r * 256;            // 0..1023
        int n = u >> 3;                   // row 0..127
        int jj = u & 7;                   // 16B unit
        int h = hbase + n;
        int idx = 0;
        uint32_t sz = 0;
        if (h < HX) {
            if (s == 0) { idx = h; sz = 16; }
            else {
                int t = __ldg(nb + h * KNB + (s - 1));
                if (t >= 0) { idx = t; sz = 16; }
            }
        }
        const char* src = (const char*)(g_xTh + ((size_t)b * HX + idx) * CIN) + jj * 16;
        uint32_t dst = buf + (uint32_t)(n * 128) + (uint32_t)((jj ^ (n & 7)) * 16);
        cp16cg(dst, src, sz);
    }
}

// ---------------- main persistent kernel: 256 thr, 2 CTAs/SM ----------------
// Each CTA owns a fixed M-half (64 output rows, A resident in smem).
// CTA tile 64M x 128N; warp grid 2M x 4N; warp tile 32x32 (validated body).
__global__ void __launch_bounds__(256, 2)
hexconv_main(const int* __restrict__ nb, const float* __restrict__ bias,
             float* __restrict__ out) {
    extern __shared__ __align__(1024) char smem[];
    const uint32_t smA = s2u(smem);
    const uint32_t smB = smA + A_BYTES;

    const int tid  = threadIdx.x;
    const int wid  = tid >> 5;
    const int lane = tid & 31;
    const int mhalf  = blockIdx.x & 1;
    const int ctaIdx = blockIdx.x >> 1;
    const int nH     = gridDim.x >> 1;

    const int ntiles_cta = (TOT2 - ctaIdx + nH - 1) / nH;
    const int nchunks = ntiles_cta * NSLOT;

    // ---- A prologue: resident W rows [mhalf*64, mhalf*64+64) ----
#pragma unroll
    for (int j = 0; j < 14; j++) {
        int i = j * 256 + tid;            // 0..3583
        int m = i / 56, u = i - m * 56;
        uint32_t dst = smA + (uint32_t)m * ROWB + (((uint32_t)u ^ (uint32_t)(m & 7)) * 16);
        const char* src = (const char*)g_Wh + (size_t)(mhalf * 64 + m) * ROWB + u * 16;
        cp16ca(dst, src);
    }

    // ---- ahead cursor + prologue chunks (A rides in group 0) ----
    int w_a = ctaIdx;
    int b_a = w_a / TPB;
    int hb_a = (w_a - b_a * TPB) * NTILE;
    int s_a = 0, q_a = 0;
#pragma unroll 1
    for (int j = 0; j < LOOKAHEAD; j++) {
        gather_chunk(smB + (uint32_t)q_a * CHUNK_B, nb, b_a, hb_a, s_a, tid);
        cp_commit();
        if (++s_a == NSLOT) { s_a = 0; w_a += nH; b_a = w_a / TPB; hb_a = (w_a - b_a * TPB) * NTILE; }
        if (++q_a == NSTAGE) q_a = 0;
    }

    // ---- per-warp MMA constants ----
    const uint32_t m0 = (uint32_t)(wid & 1) * 32;        // local M offset (0/32)
    const uint32_t n0 = (uint32_t)(wid >> 1) * 32;       // N offset (0/32/64/96)
    const uint32_t arow  = (lane & 7) + ((lane >> 3) & 1) * 8;
    const uint32_t aksel = (uint32_t)(lane >> 4);
    const uint32_t ar7   = arow & 7;
    const uint32_t a0base = smA + (m0 + arow) * ROWB;
    const uint32_t a1base = a0base + 16 * ROWB;
    const uint32_t nrow  = (lane & 7) + ((lane >> 4) & 1) * 8;
    const uint32_t bksel = (uint32_t)((lane >> 3) & 1);
    const uint32_t br7   = nrow & 7;
    const uint32_t boff0 = (n0 + nrow) * 128;

    // epilogue constants
    const int mg   = mhalf * 64 + (int)m0;    // global output row base for this warp
    const int qq   = lane >> 2;
    const int col0 = 2 * (lane & 3);
    const float bia0 = bias[mg + qq];
    const float bia1 = bias[mg + qq + 8];
    const float bia2 = bias[mg + qq + 16];
    const float bia3 = bias[mg + qq + 24];

    // ---- consume cursor ----
    int w_c = ctaIdx;
    int b_c = w_c / TPB;
    int hb_c = (w_c - b_c * TPB) * NTILE;
    int s_c = 0, q_c = 0;

    float acc[2][4][4];
#pragma unroll
    for (int mf = 0; mf < 2; mf++)
#pragma unroll
        for (int nf = 0; nf < 4; nf++)
#pragma unroll
            for (int e = 0; e < 4; e++) acc[mf][nf][e] = 0.0f;

    for (int c = 0; c < nchunks; c++) {
        cp_wait1();
        __syncthreads();

        if (c + LOOKAHEAD < nchunks) {
            gather_chunk(smB + (uint32_t)q_a * CHUNK_B, nb, b_a, hb_a, s_a, tid);
            if (++s_a == NSLOT) { s_a = 0; w_a += nH; b_a = w_a / TPB; hb_a = (w_a - b_a * TPB) * NTILE; }
            if (++q_a == NSTAGE) q_a = 0;
        }
        cp_commit();   // uniform group count

        // ---- MMA: 4 k-steps; A slice = slot s_c of resident A ----
        const uint32_t bufB = smB + (uint32_t)q_c * CHUNK_B;
        const uint32_t aunit = (uint32_t)s_c * 8;
#pragma unroll
        for (int ksl = 0; ksl < 4; ksl++) {
            uint32_t ua = (((aunit + 2u * ksl + aksel) ^ ar7) * 16);
            uint32_t ub = (((2u * ksl + bksel) ^ br7) * 16);
            uint32_t aA[4], aB[4], bb0[4], bb1[4];
            ldsm4(aA, a0base + ua);
            ldsm4(aB, a1base + ua);
            ldsm4(bb0, bufB + boff0 + ub);
            ldsm4(bb1, bufB + boff0 + 16 * 128 + ub);
            mma16816(acc[0][0], aA, bb0[0], bb0[1]);
            mma16816(acc[0][1], aA, bb0[2], bb0[3]);
            mma16816(acc[0][2], aA, bb1[0], bb1[1]);
            mma16816(acc[0][3], aA, bb1[2], bb1[3]);
            mma16816(acc[1][0], aB, bb0[0], bb0[1]);
            mma16816(acc[1][1], aB, bb0[2], bb0[3]);
            mma16816(acc[1][2], aB, bb1[0], bb1[1]);
            mma16816(acc[1][3], aB, bb1[2], bb1[3]);
        }
        if (++q_c == NSTAGE) q_c = 0;

        if (++s_c == NSLOT) {
            // ---- epilogue for tile (b_c, hb_c): scalar stores (HX odd) ----
            float* outB = out + (size_t)b_c * COUT * HX;
#pragma unroll
            for (int mf = 0; mf < 2; mf++) {
                const float blo = mf ? bia2 : bia0;
                const float bhi = mf ? bia3 : bia1;
                float* r0 = outB + (size_t)(mg + 16 * mf + qq) * HX;
                float* r1 = r0 + 8 * (size_t)HX;
#pragma unroll
                for (int nf = 0; nf < 4; nf++) {
                    int hh = hb_c + (int)n0 + 8 * nf + col0;
                    if (hh < HX) {
                        float i0 = g_invd[hh];
                        r0[hh] = acc[mf][nf][0] * i0 + blo;
                        r1[hh] = acc[mf][nf][2] * i0 + bhi;
                    }
                    if (hh + 1 < HX) {
                        float i1 = g_invd[hh + 1];
                        r0[hh + 1] = acc[mf][nf][1] * i1 + blo;
                        r1[hh + 1] = acc[mf][nf][3] * i1 + bhi;
                    }
                }
            }
#pragma unroll
            for (int mf = 0; mf < 2; mf++)
#pragma unroll
                for (int nf = 0; nf < 4; nf++)
#pragma unroll
                    for (int e = 0; e < 4; e++) acc[mf][nf][e] = 0.0f;
            s_c = 0;
            w_c += nH;
            b_c = w_c / TPB;
            hb_c = (w_c - b_c * TPB) * NTILE;
        }
    }
}

// ---------------- launch ----------------
extern "C" void kernel_launch(void* const* d_in, const int* in_sizes, int n_in,
                              void* d_out, int out_size) {
    const float* x    = (const float*)d_in[0];
    const int*   nb   = (const int*)d_in[1];
    const float* wc   = (const float*)d_in[2];
    const float* wn   = (const float*)d_in[3];
    const float* bias = (const float*)d_in[4];
    float* out = (float*)d_out;

    int nsm = 148;
    cudaDeviceGetAttribute(&nsm, cudaDevAttrMultiProcessorCount, 0);

    cudaFuncSetAttribute(hexconv_main, cudaFuncAttributeMaxDynamicSharedMemorySize, SMEM_TOTAL);

    prep_xTh<<<(BATCH * HX + 255) / 256, 256>>>(x);
    prep_misc<<<(COUT * KD + 255) / 256, 256>>>(wc, wn, nb);
    hexconv_main<<<2 * nsm, 256, SMEM_TOTAL>>>(nb, bias, out);
}